// round 16
// baseline (speedup 1.0000x reference)
#include <cuda_runtime.h>
#include <cuda_fp16.h>
#include <cstdint>

#define BS 32
#define PP 128
#define RR 16
#define DD 1024
#define RHO 0.97f
#define MM (BS * PP)   // 4096 rows of the big GEMM

// ---------------- scratch (no allocations allowed) ----------------
__device__ __half g_Ch[(size_t)MM * DD];             // k_cand fp16 (8 MB)
__device__ __half g_Ah[(size_t)MM * DD];             // x fp16 (8 MB)
__device__ __half g_Bh[(size_t)DD * DD];             // Wk fp16 [K][N] (2 MB)
__device__ float g_normp[MM * 32];                   // per-row sumsq partials
__device__ float g_w[MM];
__device__ float g_Atot[BS];
__device__ float g_wsum[BS];
__device__ float g_hbarp[8 * BS * DD];               // p-split partials
__device__ float g_eligKp[8 * BS * DD];              // p-split partials
__device__ float g_eligVp[16 * BS * DD];             // k-split partials

// ---------------- PTX helpers ----------------
__device__ __forceinline__ uint32_t smem_u32(const void* p) {
    return (uint32_t)__cvta_generic_to_shared(p);
}
__device__ __forceinline__ void cp_async16(uint32_t dst, const void* src) {
    asm volatile("cp.async.cg.shared.global [%0], [%1], 16;" :: "r"(dst), "l"(src));
}
#define CP_COMMIT() asm volatile("cp.async.commit_group;" ::: "memory")
#define CP_WAIT2()  asm volatile("cp.async.wait_group 2;" ::: "memory")
#define CP_WAIT0()  asm volatile("cp.async.wait_group 0;" ::: "memory")

__device__ __forceinline__ void ldm_x4(uint32_t* r, uint32_t addr) {
    asm volatile("ldmatrix.sync.aligned.m8n8.x4.shared.b16 {%0,%1,%2,%3}, [%4];"
                 : "=r"(r[0]), "=r"(r[1]), "=r"(r[2]), "=r"(r[3]) : "r"(addr));
}
__device__ __forceinline__ void ldm_x4_t(uint32_t& r0, uint32_t& r1, uint32_t& r2,
                                         uint32_t& r3, uint32_t addr) {
    asm volatile("ldmatrix.sync.aligned.m8n8.x4.trans.shared.b16 {%0,%1,%2,%3}, [%4];"
                 : "=r"(r0), "=r"(r1), "=r"(r2), "=r"(r3) : "r"(addr));
}
__device__ __forceinline__ void mma_f16(float* c, const uint32_t* a, const uint32_t* b) {
    asm volatile("mma.sync.aligned.m16n8k16.row.col.f32.f16.f16.f32 "
                 "{%0,%1,%2,%3}, {%4,%5,%6,%7}, {%8,%9}, {%0,%1,%2,%3};"
                 : "+f"(c[0]), "+f"(c[1]), "+f"(c[2]), "+f"(c[3])
                 : "r"(a[0]), "r"(a[1]), "r"(a[2]), "r"(a[3]), "r"(b[0]), "r"(b[1]));
}

// ---------------- 1) per-batch coefficients ----------------
__global__ void coeff_kernel(const float* __restrict__ surprise,
                             const unsigned int* __restrict__ mask) {
    int b = blockIdx.x, p = threadIdx.x;  // 128 threads
    __shared__ float a_s[PP], c_s[PP], w_s[PP];
    float g = fminf(fmaxf(surprise[b * PP + p] * 0.2f, 0.0f), 1.0f);
    float a = (mask[b * PP + p] != 0u) ? 0.0f : RHO;
    a_s[p] = a;
    __syncthreads();
    if (p == 0) {
        float c = 1.0f;
        for (int q = PP - 1; q >= 0; --q) { c_s[q] = c; c *= a_s[q]; }
        g_Atot[b] = c;
    }
    __syncthreads();
    float w = g * c_s[p];
    w_s[p] = w;
    g_w[b * PP + p] = w;
    __syncthreads();
    if (p == 0) {
        float s = 0.0f;
        for (int q = 0; q < PP; q++) s += w_s[q];
        g_wsum[b] = s;
    }
}

// ---------------- 2) fp32 -> fp16 conversions (8 elems/thread) ----------------
__global__ __launch_bounds__(256) void convA_kernel(const float* __restrict__ x) {
    size_t i8 = (size_t)blockIdx.x * 256 + threadIdx.x;  // over MM*DD/8
    const float4* xf = (const float4*)x;
    float4 a = xf[i8 * 2], b = xf[i8 * 2 + 1];
    __half2 h0 = __floats2half2_rn(a.x, a.y);
    __half2 h1 = __floats2half2_rn(a.z, a.w);
    __half2 h2 = __floats2half2_rn(b.x, b.y);
    __half2 h3 = __floats2half2_rn(b.z, b.w);
    *(uint4*)&g_Ah[i8 * 8] = make_uint4(*(uint32_t*)&h0, *(uint32_t*)&h1,
                                        *(uint32_t*)&h2, *(uint32_t*)&h3);
}
__global__ __launch_bounds__(256) void convB_kernel(const float* __restrict__ Wk) {
    size_t i8 = (size_t)blockIdx.x * 256 + threadIdx.x;  // over DD*DD/8
    const float4* xf = (const float4*)Wk;
    float4 a = xf[i8 * 2], b = xf[i8 * 2 + 1];
    __half2 h0 = __floats2half2_rn(a.x, a.y);
    __half2 h1 = __floats2half2_rn(a.z, a.w);
    __half2 h2 = __floats2half2_rn(b.x, b.y);
    __half2 h3 = __floats2half2_rn(b.z, b.w);
    *(uint4*)&g_Bh[i8 * 8] = make_uint4(*(uint32_t*)&h0, *(uint32_t*)&h1,
                                        *(uint32_t*)&h2, *(uint32_t*)&h3);
}

// ---------------- 3) readout: y_pm — two-phase, 64 KB smem, 16 tokens/block ----
// Phase 1: stage K (64 KB), compute dots+weights into ws. Phase 2: overwrite
// the same smem with V, combine. Halved smem -> 3 CTAs/SM cap; grid (BS,8)
// = 256 blocks -> ~2 resident CTAs/SM (was 1), doubling LDS-issue parallelism.
__global__ __launch_bounds__(256) void readout_kernel(const float* __restrict__ x,
                                                      const float* __restrict__ pmK,
                                                      const float* __restrict__ pmV,
                                                      const float* __restrict__ pa,
                                                      float* __restrict__ y) {
    extern __shared__ float sm[];            // RR*DD floats = 64 KB
    __shared__ float pas[RR];
    __shared__ float ws[16][17];
    int b = blockIdx.x;
    int tid = threadIdx.x;
    int warp = tid >> 5, lane = tid & 31;

    // stage K
    const float4* Kg = (const float4*)(pmK + (size_t)b * RR * DD);
    float4* S4 = (float4*)sm;
    for (int i = tid; i < RR * DD / 4; i += 256) S4[i] = Kg[i];
    if (tid < RR) pas[tid] = pa[b * RR + tid];
    __syncthreads();

    // phase 1: dots for this block's 16 tokens (2 per warp)
    for (int t0 = 0; t0 < 16; t0 += 8) {
        int tok = t0 + warp;
        int p = blockIdx.y * 16 + tok;
        const float4* xr = (const float4*)(x + ((size_t)b * PP + p) * DD);
        float nrm = 0.0f;
        float dot[16];
#pragma unroll
        for (int r = 0; r < 16; r++) dot[r] = 0.0f;
#pragma unroll 2
        for (int c = 0; c < 8; c++) {
            float4 v = xr[c * 32 + lane];
            nrm += v.x * v.x + v.y * v.y + v.z * v.z + v.w * v.w;
#pragma unroll
            for (int r = 0; r < 16; r++) {
                float4 kv = ((const float4*)(sm + r * DD))[c * 32 + lane];
                dot[r] += v.x * kv.x + v.y * kv.y + v.z * kv.z + v.w * kv.w;
            }
        }
#pragma unroll
        for (int off = 16; off; off >>= 1) {
            nrm += __shfl_xor_sync(0xFFFFFFFFu, nrm, off);
#pragma unroll
            for (int r = 0; r < 16; r++)
                dot[r] += __shfl_xor_sync(0xFFFFFFFFu, dot[r], off);
        }
        float inv = 1.0f / fmaxf(sqrtf(nrm), 1e-8f);
        if (lane == 0) {
#pragma unroll
            for (int r = 0; r < 16; r++) ws[tok][r] = pas[r] * dot[r] * inv;
        }
    }
    __syncthreads();

    // stage V (overwrite)
    const float4* Vg = (const float4*)(pmV + (size_t)b * RR * DD);
    for (int i = tid; i < RR * DD / 4; i += 256) S4[i] = Vg[i];
    __syncthreads();

    // phase 2: combine
    for (int t0 = 0; t0 < 16; t0 += 8) {
        int tok = t0 + warp;
        int p = blockIdx.y * 16 + tok;
        float w[16];
#pragma unroll
        for (int r = 0; r < 16; r++) w[r] = ws[tok][r];
        float4* yo = (float4*)(y + ((size_t)b * PP + p) * DD);
#pragma unroll 2
        for (int c = 0; c < 8; c++) {
            float4 acc = {0.f, 0.f, 0.f, 0.f};
#pragma unroll
            for (int r = 0; r < 16; r++) {
                float4 vv = ((const float4*)(sm + r * DD))[c * 32 + lane];
                acc.x += w[r] * vv.x;
                acc.y += w[r] * vv.y;
                acc.z += w[r] * vv.z;
                acc.w += w[r] * vv.w;
            }
            yo[c * 32 + lane] = acc;
        }
    }
}

// ---------------- 4) single-fp16 mma.sync GEMM, 4-stage cp.async ----------------
#define ASTB 80
#define BSTB 272
#define ASTG_A 10240
#define STAGE_B 18944
#define NSTAGE 4
#define GSMEM (NSTAGE * STAGE_B)

__global__ __launch_bounds__(256) void mma_gemm_kernel(const float* __restrict__ bias) {
    extern __shared__ char smem[];
    uint32_t sb = smem_u32(smem);
    int tid = threadIdx.x;
    int lane = tid & 31, warp = tid >> 5;
    int wm = warp >> 2, wn = warp & 3;
    int bm = blockIdx.y * 128, bn = blockIdx.x * 128;

    float acc[4][4][4];
#pragma unroll
    for (int i = 0; i < 4; i++)
#pragma unroll
        for (int j = 0; j < 4; j++)
#pragma unroll
            for (int k = 0; k < 4; k++) acc[i][j][k] = 0.0f;

    int aid0 = tid * 2;
    int arow0 = aid0 >> 2, ach0 = aid0 & 3;
    int arow1 = (aid0 + 1) >> 2, ach1 = (aid0 + 1) & 3;
    int brow0 = aid0 >> 4, bch0 = aid0 & 15;
    int brow1 = (aid0 + 1) >> 4, bch1 = (aid0 + 1) & 15;

    auto issue_stage = [&](int kt, int slot) {
        int ak = kt * 32;
        uint32_t sA = sb + slot * STAGE_B;
        uint32_t sB = sA + ASTG_A;
        cp_async16(sA + arow0 * ASTB + ach0 * 16,
                   &g_Ah[(size_t)(bm + arow0) * 1024 + ak + ach0 * 8]);
        cp_async16(sA + arow1 * ASTB + ach1 * 16,
                   &g_Ah[(size_t)(bm + arow1) * 1024 + ak + ach1 * 8]);
        cp_async16(sB + brow0 * BSTB + bch0 * 16,
                   &g_Bh[(size_t)(ak + brow0) * 1024 + bn + bch0 * 8]);
        cp_async16(sB + brow1 * BSTB + bch1 * 16,
                   &g_Bh[(size_t)(ak + brow1) * 1024 + bn + bch1 * 8]);
    };

    int g8 = lane >> 3;
    int r8 = lane & 7;
    int aRowOff = wm * 64 + r8 + (g8 & 1) * 8;
    int aColB = (g8 >> 1) * 16;
    int bRowOff = r8 + (g8 & 1) * 8;
    int bColB = (wn * 32 + (g8 >> 1) * 8) * 2;

#pragma unroll
    for (int i = 0; i < NSTAGE - 1; i++) {
        issue_stage(i, i);
        CP_COMMIT();
    }

    for (int i = 0; i < 32; i++) {
        CP_WAIT2();
        __syncthreads();
        int slot = i & (NSTAGE - 1);
        uint32_t sA = sb + slot * STAGE_B;
        uint32_t sB = sA + ASTG_A;
#pragma unroll
        for (int ks = 0; ks < 32; ks += 16) {
            uint32_t afr[4][4], bfr[4][2];
#pragma unroll
            for (int tm = 0; tm < 4; tm++)
                ldm_x4(afr[tm], sA + (aRowOff + tm * 16) * ASTB + aColB + ks * 2);
#pragma unroll
            for (int tp = 0; tp < 2; tp++) {
                uint32_t r0, r1, r2, r3;
                ldm_x4_t(r0, r1, r2, r3,
                         sB + (bRowOff + ks) * BSTB + bColB + tp * 32);
                bfr[tp * 2][0] = r0; bfr[tp * 2][1] = r1;
                bfr[tp * 2 + 1][0] = r2; bfr[tp * 2 + 1][1] = r3;
            }
#pragma unroll
            for (int tm = 0; tm < 4; tm++)
#pragma unroll
                for (int tn = 0; tn < 4; tn++)
                    mma_f16(acc[tm][tn], afr[tm], bfr[tn]);
        }
        if (i + NSTAGE - 1 < 32) issue_stage(i + NSTAGE - 1, (i + NSTAGE - 1) & (NSTAGE - 1));
        CP_COMMIT();
    }
    CP_WAIT0();

    int gq = lane >> 2;
    int cq = lane & 3;
#pragma unroll
    for (int tm = 0; tm < 4; tm++) {
        int row0 = bm + wm * 64 + tm * 16 + gq;
        float s0 = 0.0f, s1 = 0.0f;
#pragma unroll
        for (int tn = 0; tn < 4; tn++) {
            int col = bn + wn * 32 + tn * 8 + cq * 2;
            float2 bb = *(const float2*)&bias[col];
            float v0 = acc[tm][tn][0] + bb.x;
            float v1 = acc[tm][tn][1] + bb.y;
            float v2 = acc[tm][tn][2] + bb.x;
            float v3 = acc[tm][tn][3] + bb.y;
            *(__half2*)&g_Ch[(size_t)row0 * DD + col] = __floats2half2_rn(v0, v1);
            *(__half2*)&g_Ch[(size_t)(row0 + 8) * DD + col] = __floats2half2_rn(v2, v3);
            s0 += v0 * v0 + v1 * v1;
            s1 += v2 * v2 + v3 * v3;
        }
        s0 += __shfl_xor_sync(0xFFFFFFFFu, s0, 1);
        s0 += __shfl_xor_sync(0xFFFFFFFFu, s0, 2);
        s1 += __shfl_xor_sync(0xFFFFFFFFu, s1, 1);
        s1 += __shfl_xor_sync(0xFFFFFFFFu, s1, 2);
        if (cq == 0) {
            int slot = blockIdx.x * 4 + wn;
            g_normp[(size_t)row0 * 32 + slot] = s0;
            g_normp[(size_t)(row0 + 8) * 32 + slot] = s1;
        }
    }
}

// ---------------- 5) hbar partials: grid (BS, 1, 8), float4 loads ----------------
__global__ __launch_bounds__(256) void hbar_kernel(const float* __restrict__ h) {
    int b = blockIdx.x, s = blockIdx.z;
    int t = threadIdx.x;
    __shared__ float cs[16];
    if (t < 16) cs[t] = g_w[b * PP + s * 16 + t];
    __syncthreads();
    const float4* sp = (const float4*)(h + ((size_t)b * PP + s * 16) * DD) + t;
    float4 acc = {0.f, 0.f, 0.f, 0.f};
#pragma unroll
    for (int p = 0; p < 16; p++) {
        float4 v = sp[(size_t)p * 256];
        float c = cs[p];
        acc.x += c * v.x; acc.y += c * v.y; acc.z += c * v.z; acc.w += c * v.w;
    }
    ((float4*)&g_hbarp[((s * BS + b) << 10)])[t] = acc;
}

// ---------------- 6) eligK partials + inline coefK: grid (BS, 2, 8) ----------------
__global__ __launch_bounds__(256) void eligk_kernel() {
    int b = blockIdx.x, s = blockIdx.z;
    int d2 = blockIdx.y * 256 + threadIdx.x;  // half2 index 0..511
    __shared__ float cs[16];
    if (threadIdx.x < 16) {
        int row = b * PP + s * 16 + threadIdx.x;
        const float* p = &g_normp[row * 32];
        float ss = 0.0f;
#pragma unroll
        for (int i = 0; i < 32; i++) ss += p[i];
        cs[threadIdx.x] = g_w[row] / fmaxf(sqrtf(ss), 1e-8f);
    }
    __syncthreads();
    const __half2* sp = (const __half2*)g_Ch + ((size_t)b * PP + s * 16) * (DD / 2) + d2;
    float2 acc = {0.f, 0.f};
#pragma unroll
    for (int p = 0; p < 16; p++) {
        float2 v = __half22float2(sp[(size_t)p * (DD / 2)]);
        float c = cs[p];
        acc.x += c * v.x;
        acc.y += c * v.y;
    }
    int base = ((s * BS + b) << 10) + d2 * 2;
    g_eligKp[base] = acc.x;
    g_eligKp[base + 1] = acc.y;
}

// ---------------- 7) eligV split-K partials: grid (8 col-chunks, 16 k-chunks) ----------------
__global__ __launch_bounds__(256) void vgemm_kernel(const float* __restrict__ Wv) {
    __shared__ float hs[BS][64];       // 8 KB
    __shared__ float red[BS][128];     // 16 KB
    int ec = blockIdx.x, kc = blockIdx.y;
    int k0 = kc * 64;
    int t = threadIdx.x;
    int col = ec * 128 + (t & 127);
    int half = t >> 7;                 // k-subrange 0/1

    for (int i = t; i < BS * 64; i += 256) {
        int b = i >> 6, k = i & 63;
        float v = 0.0f;
#pragma unroll
        for (int s = 0; s < 8; s++) v += g_hbarp[((s * BS + b) << 10) + k0 + k];
        hs[b][k] = v;
    }
    __syncthreads();

    float acc[BS];
#pragma unroll
    for (int b = 0; b < BS; b++) acc[b] = 0.0f;
#pragma unroll 4
    for (int k = 0; k < 32; k++) {
        int kk = half * 32 + k;
        float wv = Wv[(size_t)(k0 + kk) * DD + col];
#pragma unroll
        for (int b = 0; b < BS; b++) acc[b] += hs[b][kk] * wv;
    }
    if (half == 0) {
#pragma unroll
        for (int b = 0; b < BS; b++) red[b][t] = acc[b];
    }
    __syncthreads();
    if (half == 1) {
        int tc = t & 127;
#pragma unroll
        for (int b = 0; b < BS; b++)
            g_eligVp[((kc * BS + b) << 10) + col] = red[b][tc] + acc[b];
    }
}

// ---------------- 8) expand to [BS,R,D] outputs ----------------
__global__ __launch_bounds__(256) void expand_kernel(const float* __restrict__ eK0,
                                                     const float* __restrict__ eV0,
                                                     const float* __restrict__ bv,
                                                     float* __restrict__ outK,
                                                     float* __restrict__ outV) {
    int idx = blockIdx.x * 256 + threadIdx.x;
    if (idx >= BS * RR * DD) return;
    int b = idx / (RR * DD);
    int d = idx & (DD - 1);
    float A = g_Atot[b];
    float ek = 0.0f;
#pragma unroll
    for (int s = 0; s < 8; s++) ek += g_eligKp[((s * BS + b) << 10) + d];
    float ev = g_wsum[b] * bv[d];
#pragma unroll
    for (int kc = 0; kc < 16; kc++) ev += g_eligVp[((kc * BS + b) << 10) + d];
    outK[idx] = A * eK0[idx] + ek;
    outV[idx] = A * eV0[idx] + ev;
}

// ---------------- launch ----------------
extern "C" void kernel_launch(void* const* d_in, const int* in_sizes, int n_in,
                              void* d_out, int out_size) {
    const float* x = (const float*)d_in[0];
    const float* h = (const float*)d_in[1];
    const float* sur = (const float*)d_in[2];
    const unsigned int* mask = (const unsigned int*)d_in[3];
    const float* pmK = (const float*)d_in[4];
    const float* pmV = (const float*)d_in[5];
    const float* pa = (const float*)d_in[6];
    const float* eK0 = (const float*)d_in[7];
    const float* eV0 = (const float*)d_in[8];
    const float* Wk = (const float*)d_in[9];
    const float* bk = (const float*)d_in[10];
    const float* Wv = (const float*)d_in[11];
    const float* bv = (const float*)d_in[12];

    float* out = (float*)d_out;
    float* y = out;
    float* outK = out + (size_t)BS * PP * DD;
    float* outV = outK + (size_t)BS * RR * DD;

    static const int READOUT_SMEM = RR * DD * (int)sizeof(float);  // 64 KB
    cudaFuncSetAttribute(readout_kernel,
                         cudaFuncAttributeMaxDynamicSharedMemorySize, READOUT_SMEM);
    cudaFuncSetAttribute(mma_gemm_kernel,
                         cudaFuncAttributeMaxDynamicSharedMemorySize, GSMEM);

    coeff_kernel<<<BS, PP>>>(sur, mask);
    convA_kernel<<<MM * DD / 8 / 256, 256>>>(x);
    convB_kernel<<<DD * DD / 8 / 256, 256>>>(Wk);
    readout_kernel<<<dim3(BS, PP / 16), 256, READOUT_SMEM>>>(x, pmK, pmV, pa, y);
    mma_gemm_kernel<<<dim3(DD / 128, MM / 128), 256, GSMEM>>>(bk);
    hbar_kernel<<<dim3(BS, 1, 8), 256>>>(h);
    eligk_kernel<<<dim3(BS, 2, 8), 256>>>();
    vgemm_kernel<<<dim3(8, 16), 256>>>(Wv);
    expand_kernel<<<(BS * RR * DD + 255) / 256, 256>>>(eK0, eV0, bv, outK, outV);
}

// round 17
// speedup vs baseline: 1.0769x; 1.0769x over previous
#include <cuda_runtime.h>
#include <cuda_fp16.h>
#include <cstdint>

#define BS 32
#define PP 128
#define RR 16
#define DD 1024
#define RHO 0.97f
#define MM (BS * PP)   // 4096 rows of the big GEMM

// ---------------- scratch (no allocations allowed) ----------------
__device__ __half g_Ch[(size_t)MM * DD];             // k_cand fp16 (8 MB)
__device__ __half g_Ah[(size_t)MM * DD];             // x fp16 (8 MB)
__device__ __half g_Bh[(size_t)DD * DD];             // Wk fp16 [K][N] (2 MB)
__device__ float g_normp[MM * 32];                   // per-row sumsq partials
__device__ float g_w[MM];
__device__ float g_Atot[BS];
__device__ float g_wsum[BS];
__device__ float g_hbarp[8 * BS * DD];               // p-split partials
__device__ float g_eligKp[8 * BS * DD];              // p-split partials
__device__ float g_eligVp[16 * BS * DD];             // k-split partials

// ---------------- PTX helpers ----------------
__device__ __forceinline__ uint32_t smem_u32(const void* p) {
    return (uint32_t)__cvta_generic_to_shared(p);
}
__device__ __forceinline__ void cp_async16(uint32_t dst, const void* src) {
    asm volatile("cp.async.cg.shared.global [%0], [%1], 16;" :: "r"(dst), "l"(src));
}
#define CP_COMMIT() asm volatile("cp.async.commit_group;" ::: "memory")
#define CP_WAIT2()  asm volatile("cp.async.wait_group 2;" ::: "memory")
#define CP_WAIT0()  asm volatile("cp.async.wait_group 0;" ::: "memory")

__device__ __forceinline__ void ldm_x4(uint32_t* r, uint32_t addr) {
    asm volatile("ldmatrix.sync.aligned.m8n8.x4.shared.b16 {%0,%1,%2,%3}, [%4];"
                 : "=r"(r[0]), "=r"(r[1]), "=r"(r[2]), "=r"(r[3]) : "r"(addr));
}
__device__ __forceinline__ void ldm_x4_t(uint32_t& r0, uint32_t& r1, uint32_t& r2,
                                         uint32_t& r3, uint32_t addr) {
    asm volatile("ldmatrix.sync.aligned.m8n8.x4.trans.shared.b16 {%0,%1,%2,%3}, [%4];"
                 : "=r"(r0), "=r"(r1), "=r"(r2), "=r"(r3) : "r"(addr));
}
__device__ __forceinline__ void mma_f16(float* c, const uint32_t* a, const uint32_t* b) {
    asm volatile("mma.sync.aligned.m16n8k16.row.col.f32.f16.f16.f32 "
                 "{%0,%1,%2,%3}, {%4,%5,%6,%7}, {%8,%9}, {%0,%1,%2,%3};"
                 : "+f"(c[0]), "+f"(c[1]), "+f"(c[2]), "+f"(c[3])
                 : "r"(a[0]), "r"(a[1]), "r"(a[2]), "r"(a[3]), "r"(b[0]), "r"(b[1]));
}

// ---------------- 1) per-batch coefficients ----------------
__global__ void coeff_kernel(const float* __restrict__ surprise,
                             const unsigned int* __restrict__ mask) {
    int b = blockIdx.x, p = threadIdx.x;  // 128 threads
    __shared__ float a_s[PP], c_s[PP], w_s[PP];
    float g = fminf(fmaxf(surprise[b * PP + p] * 0.2f, 0.0f), 1.0f);
    float a = (mask[b * PP + p] != 0u) ? 0.0f : RHO;
    a_s[p] = a;
    __syncthreads();
    if (p == 0) {
        float c = 1.0f;
        for (int q = PP - 1; q >= 0; --q) { c_s[q] = c; c *= a_s[q]; }
        g_Atot[b] = c;
    }
    __syncthreads();
    float w = g * c_s[p];
    w_s[p] = w;
    g_w[b * PP + p] = w;
    __syncthreads();
    if (p == 0) {
        float s = 0.0f;
        for (int q = 0; q < PP; q++) s += w_s[q];
        g_wsum[b] = s;
    }
}

// ---------------- 2) fp32 -> fp16 conversions (8 elems/thread) ----------------
__global__ __launch_bounds__(256) void convA_kernel(const float* __restrict__ x) {
    size_t i8 = (size_t)blockIdx.x * 256 + threadIdx.x;  // over MM*DD/8
    const float4* xf = (const float4*)x;
    float4 a = xf[i8 * 2], b = xf[i8 * 2 + 1];
    __half2 h0 = __floats2half2_rn(a.x, a.y);
    __half2 h1 = __floats2half2_rn(a.z, a.w);
    __half2 h2 = __floats2half2_rn(b.x, b.y);
    __half2 h3 = __floats2half2_rn(b.z, b.w);
    *(uint4*)&g_Ah[i8 * 8] = make_uint4(*(uint32_t*)&h0, *(uint32_t*)&h1,
                                        *(uint32_t*)&h2, *(uint32_t*)&h3);
}
__global__ __launch_bounds__(256) void convB_kernel(const float* __restrict__ Wk) {
    size_t i8 = (size_t)blockIdx.x * 256 + threadIdx.x;  // over DD*DD/8
    const float4* xf = (const float4*)Wk;
    float4 a = xf[i8 * 2], b = xf[i8 * 2 + 1];
    __half2 h0 = __floats2half2_rn(a.x, a.y);
    __half2 h1 = __floats2half2_rn(a.z, a.w);
    __half2 h2 = __floats2half2_rn(b.x, b.y);
    __half2 h3 = __floats2half2_rn(b.z, b.w);
    *(uint4*)&g_Bh[i8 * 8] = make_uint4(*(uint32_t*)&h0, *(uint32_t*)&h1,
                                        *(uint32_t*)&h2, *(uint32_t*)&h3);
}

// ---------------- 3) readout: y_pm — two-phase, 64 KB smem, 16 tokens/block ----
// Each warp owns tokens (warp, warp+8) and processes BOTH in one pass, so every
// K/V float4 smem load is reused for two tokens — halves LDS traffic vs R16.
__global__ __launch_bounds__(256) void readout_kernel(const float* __restrict__ x,
                                                      const float* __restrict__ pmK,
                                                      const float* __restrict__ pmV,
                                                      const float* __restrict__ pa,
                                                      float* __restrict__ y) {
    extern __shared__ float sm[];            // RR*DD floats = 64 KB
    __shared__ float pas[RR];
    __shared__ float ws[16][17];
    int b = blockIdx.x;
    int tid = threadIdx.x;
    int warp = tid >> 5, lane = tid & 31;

    // stage K
    const float4* Kg = (const float4*)(pmK + (size_t)b * RR * DD);
    float4* S4 = (float4*)sm;
    for (int i = tid; i < RR * DD / 4; i += 256) S4[i] = Kg[i];
    if (tid < RR) pas[tid] = pa[b * RR + tid];
    __syncthreads();

    int p0 = blockIdx.y * 16 + warp;       // token A
    int p1 = p0 + 8;                       // token B
    const float4* xr0 = (const float4*)(x + ((size_t)b * PP + p0) * DD);
    const float4* xr1 = (const float4*)(x + ((size_t)b * PP + p1) * DD);

    // phase 1: dots for both tokens, K loaded once
    {
        float nrm0 = 0.0f, nrm1 = 0.0f;
        float dot0[16], dot1[16];
#pragma unroll
        for (int r = 0; r < 16; r++) { dot0[r] = 0.0f; dot1[r] = 0.0f; }
#pragma unroll 2
        for (int c = 0; c < 8; c++) {
            float4 v0 = xr0[c * 32 + lane];
            float4 v1 = xr1[c * 32 + lane];
            nrm0 += v0.x * v0.x + v0.y * v0.y + v0.z * v0.z + v0.w * v0.w;
            nrm1 += v1.x * v1.x + v1.y * v1.y + v1.z * v1.z + v1.w * v1.w;
#pragma unroll
            for (int r = 0; r < 16; r++) {
                float4 kv = ((const float4*)(sm + r * DD))[c * 32 + lane];
                dot0[r] += v0.x * kv.x + v0.y * kv.y + v0.z * kv.z + v0.w * kv.w;
                dot1[r] += v1.x * kv.x + v1.y * kv.y + v1.z * kv.z + v1.w * kv.w;
            }
        }
#pragma unroll
        for (int off = 16; off; off >>= 1) {
            nrm0 += __shfl_xor_sync(0xFFFFFFFFu, nrm0, off);
            nrm1 += __shfl_xor_sync(0xFFFFFFFFu, nrm1, off);
#pragma unroll
            for (int r = 0; r < 16; r++) {
                dot0[r] += __shfl_xor_sync(0xFFFFFFFFu, dot0[r], off);
                dot1[r] += __shfl_xor_sync(0xFFFFFFFFu, dot1[r], off);
            }
        }
        float inv0 = 1.0f / fmaxf(sqrtf(nrm0), 1e-8f);
        float inv1 = 1.0f / fmaxf(sqrtf(nrm1), 1e-8f);
        if (lane == 0) {
#pragma unroll
            for (int r = 0; r < 16; r++) {
                ws[warp][r] = pas[r] * dot0[r] * inv0;
                ws[warp + 8][r] = pas[r] * dot1[r] * inv1;
            }
        }
    }
    __syncthreads();

    // stage V (overwrite)
    const float4* Vg = (const float4*)(pmV + (size_t)b * RR * DD);
    for (int i = tid; i < RR * DD / 4; i += 256) S4[i] = Vg[i];
    __syncthreads();

    // phase 2: combine both tokens, V loaded once
    {
        float w0[16], w1[16];
#pragma unroll
        for (int r = 0; r < 16; r++) {
            w0[r] = ws[warp][r];
            w1[r] = ws[warp + 8][r];
        }
        float4* yo0 = (float4*)(y + ((size_t)b * PP + p0) * DD);
        float4* yo1 = (float4*)(y + ((size_t)b * PP + p1) * DD);
#pragma unroll 2
        for (int c = 0; c < 8; c++) {
            float4 a0 = {0.f, 0.f, 0.f, 0.f};
            float4 a1 = {0.f, 0.f, 0.f, 0.f};
#pragma unroll
            for (int r = 0; r < 16; r++) {
                float4 vv = ((const float4*)(sm + r * DD))[c * 32 + lane];
                a0.x += w0[r] * vv.x; a0.y += w0[r] * vv.y;
                a0.z += w0[r] * vv.z; a0.w += w0[r] * vv.w;
                a1.x += w1[r] * vv.x; a1.y += w1[r] * vv.y;
                a1.z += w1[r] * vv.z; a1.w += w1[r] * vv.w;
            }
            yo0[c * 32 + lane] = a0;
            yo1[c * 32 + lane] = a1;
        }
    }
}

// ---------------- 4) single-fp16 mma.sync GEMM, 4-stage cp.async ----------------
#define ASTB 80
#define BSTB 272
#define ASTG_A 10240
#define STAGE_B 18944
#define NSTAGE 4
#define GSMEM (NSTAGE * STAGE_B)

__global__ __launch_bounds__(256) void mma_gemm_kernel(const float* __restrict__ bias) {
    extern __shared__ char smem[];
    uint32_t sb = smem_u32(smem);
    int tid = threadIdx.x;
    int lane = tid & 31, warp = tid >> 5;
    int wm = warp >> 2, wn = warp & 3;
    int bm = blockIdx.y * 128, bn = blockIdx.x * 128;

    float acc[4][4][4];
#pragma unroll
    for (int i = 0; i < 4; i++)
#pragma unroll
        for (int j = 0; j < 4; j++)
#pragma unroll
            for (int k = 0; k < 4; k++) acc[i][j][k] = 0.0f;

    int aid0 = tid * 2;
    int arow0 = aid0 >> 2, ach0 = aid0 & 3;
    int arow1 = (aid0 + 1) >> 2, ach1 = (aid0 + 1) & 3;
    int brow0 = aid0 >> 4, bch0 = aid0 & 15;
    int brow1 = (aid0 + 1) >> 4, bch1 = (aid0 + 1) & 15;

    auto issue_stage = [&](int kt, int slot) {
        int ak = kt * 32;
        uint32_t sA = sb + slot * STAGE_B;
        uint32_t sB = sA + ASTG_A;
        cp_async16(sA + arow0 * ASTB + ach0 * 16,
                   &g_Ah[(size_t)(bm + arow0) * 1024 + ak + ach0 * 8]);
        cp_async16(sA + arow1 * ASTB + ach1 * 16,
                   &g_Ah[(size_t)(bm + arow1) * 1024 + ak + ach1 * 8]);
        cp_async16(sB + brow0 * BSTB + bch0 * 16,
                   &g_Bh[(size_t)(ak + brow0) * 1024 + bn + bch0 * 8]);
        cp_async16(sB + brow1 * BSTB + bch1 * 16,
                   &g_Bh[(size_t)(ak + brow1) * 1024 + bn + bch1 * 8]);
    };

    int g8 = lane >> 3;
    int r8 = lane & 7;
    int aRowOff = wm * 64 + r8 + (g8 & 1) * 8;
    int aColB = (g8 >> 1) * 16;
    int bRowOff = r8 + (g8 & 1) * 8;
    int bColB = (wn * 32 + (g8 >> 1) * 8) * 2;

#pragma unroll
    for (int i = 0; i < NSTAGE - 1; i++) {
        issue_stage(i, i);
        CP_COMMIT();
    }

    for (int i = 0; i < 32; i++) {
        CP_WAIT2();
        __syncthreads();
        int slot = i & (NSTAGE - 1);
        uint32_t sA = sb + slot * STAGE_B;
        uint32_t sB = sA + ASTG_A;
#pragma unroll
        for (int ks = 0; ks < 32; ks += 16) {
            uint32_t afr[4][4], bfr[4][2];
#pragma unroll
            for (int tm = 0; tm < 4; tm++)
                ldm_x4(afr[tm], sA + (aRowOff + tm * 16) * ASTB + aColB + ks * 2);
#pragma unroll
            for (int tp = 0; tp < 2; tp++) {
                uint32_t r0, r1, r2, r3;
                ldm_x4_t(r0, r1, r2, r3,
                         sB + (bRowOff + ks) * BSTB + bColB + tp * 32);
                bfr[tp * 2][0] = r0; bfr[tp * 2][1] = r1;
                bfr[tp * 2 + 1][0] = r2; bfr[tp * 2 + 1][1] = r3;
            }
#pragma unroll
            for (int tm = 0; tm < 4; tm++)
#pragma unroll
                for (int tn = 0; tn < 4; tn++)
                    mma_f16(acc[tm][tn], afr[tm], bfr[tn]);
        }
        if (i + NSTAGE - 1 < 32) issue_stage(i + NSTAGE - 1, (i + NSTAGE - 1) & (NSTAGE - 1));
        CP_COMMIT();
    }
    CP_WAIT0();

    int gq = lane >> 2;
    int cq = lane & 3;
#pragma unroll
    for (int tm = 0; tm < 4; tm++) {
        int row0 = bm + wm * 64 + tm * 16 + gq;
        float s0 = 0.0f, s1 = 0.0f;
#pragma unroll
        for (int tn = 0; tn < 4; tn++) {
            int col = bn + wn * 32 + tn * 8 + cq * 2;
            float2 bb = *(const float2*)&bias[col];
            float v0 = acc[tm][tn][0] + bb.x;
            float v1 = acc[tm][tn][1] + bb.y;
            float v2 = acc[tm][tn][2] + bb.x;
            float v3 = acc[tm][tn][3] + bb.y;
            *(__half2*)&g_Ch[(size_t)row0 * DD + col] = __floats2half2_rn(v0, v1);
            *(__half2*)&g_Ch[(size_t)(row0 + 8) * DD + col] = __floats2half2_rn(v2, v3);
            s0 += v0 * v0 + v1 * v1;
            s1 += v2 * v2 + v3 * v3;
        }
        s0 += __shfl_xor_sync(0xFFFFFFFFu, s0, 1);
        s0 += __shfl_xor_sync(0xFFFFFFFFu, s0, 2);
        s1 += __shfl_xor_sync(0xFFFFFFFFu, s1, 1);
        s1 += __shfl_xor_sync(0xFFFFFFFFu, s1, 2);
        if (cq == 0) {
            int slot = blockIdx.x * 4 + wn;
            g_normp[(size_t)row0 * 32 + slot] = s0;
            g_normp[(size_t)(row0 + 8) * 32 + slot] = s1;
        }
    }
}

// ---------------- 5) hbar partials: grid (BS, 1, 8), float4 loads ----------------
__global__ __launch_bounds__(256) void hbar_kernel(const float* __restrict__ h) {
    int b = blockIdx.x, s = blockIdx.z;
    int t = threadIdx.x;
    __shared__ float cs[16];
    if (t < 16) cs[t] = g_w[b * PP + s * 16 + t];
    __syncthreads();
    const float4* sp = (const float4*)(h + ((size_t)b * PP + s * 16) * DD) + t;
    float4 acc = {0.f, 0.f, 0.f, 0.f};
#pragma unroll
    for (int p = 0; p < 16; p++) {
        float4 v = sp[(size_t)p * 256];
        float c = cs[p];
        acc.x += c * v.x; acc.y += c * v.y; acc.z += c * v.z; acc.w += c * v.w;
    }
    ((float4*)&g_hbarp[((s * BS + b) << 10)])[t] = acc;
}

// ---------------- 6) eligK partials + inline coefK: grid (BS, 2, 8) ----------------
__global__ __launch_bounds__(256) void eligk_kernel() {
    int b = blockIdx.x, s = blockIdx.z;
    int d2 = blockIdx.y * 256 + threadIdx.x;  // half2 index 0..511
    __shared__ float cs[16];
    if (threadIdx.x < 16) {
        int row = b * PP + s * 16 + threadIdx.x;
        const float* p = &g_normp[row * 32];
        float ss = 0.0f;
#pragma unroll
        for (int i = 0; i < 32; i++) ss += p[i];
        cs[threadIdx.x] = g_w[row] / fmaxf(sqrtf(ss), 1e-8f);
    }
    __syncthreads();
    const __half2* sp = (const __half2*)g_Ch + ((size_t)b * PP + s * 16) * (DD / 2) + d2;
    float2 acc = {0.f, 0.f};
#pragma unroll
    for (int p = 0; p < 16; p++) {
        float2 v = __half22float2(sp[(size_t)p * (DD / 2)]);
        float c = cs[p];
        acc.x += c * v.x;
        acc.y += c * v.y;
    }
    int base = ((s * BS + b) << 10) + d2 * 2;
    g_eligKp[base] = acc.x;
    g_eligKp[base + 1] = acc.y;
}

// ---------------- 7) eligV split-K partials: grid (8 col-chunks, 16 k-chunks) ----------------
__global__ __launch_bounds__(256) void vgemm_kernel(const float* __restrict__ Wv) {
    __shared__ float hs[BS][64];       // 8 KB
    __shared__ float red[BS][128];     // 16 KB
    int ec = blockIdx.x, kc = blockIdx.y;
    int k0 = kc * 64;
    int t = threadIdx.x;
    int col = ec * 128 + (t & 127);
    int half = t >> 7;                 // k-subrange 0/1

    for (int i = t; i < BS * 64; i += 256) {
        int b = i >> 6, k = i & 63;
        float v = 0.0f;
#pragma unroll
        for (int s = 0; s < 8; s++) v += g_hbarp[((s * BS + b) << 10) + k0 + k];
        hs[b][k] = v;
    }
    __syncthreads();

    float acc[BS];
#pragma unroll
    for (int b = 0; b < BS; b++) acc[b] = 0.0f;
#pragma unroll 4
    for (int k = 0; k < 32; k++) {
        int kk = half * 32 + k;
        float wv = Wv[(size_t)(k0 + kk) * DD + col];
#pragma unroll
        for (int b = 0; b < BS; b++) acc[b] += hs[b][kk] * wv;
    }
    if (half == 0) {
#pragma unroll
        for (int b = 0; b < BS; b++) red[b][t] = acc[b];
    }
    __syncthreads();
    if (half == 1) {
        int tc = t & 127;
#pragma unroll
        for (int b = 0; b < BS; b++)
            g_eligVp[((kc * BS + b) << 10) + col] = red[b][tc] + acc[b];
    }
}

// ---------------- 8) expand to [BS,R,D] outputs ----------------
__global__ __launch_bounds__(256) void expand_kernel(const float* __restrict__ eK0,
                                                     const float* __restrict__ eV0,
                                                     const float* __restrict__ bv,
                                                     float* __restrict__ outK,
                                                     float* __restrict__ outV) {
    int idx = blockIdx.x * 256 + threadIdx.x;
    if (idx >= BS * RR * DD) return;
    int b = idx / (RR * DD);
    int d = idx & (DD - 1);
    float A = g_Atot[b];
    float ek = 0.0f;
#pragma unroll
    for (int s = 0; s < 8; s++) ek += g_eligKp[((s * BS + b) << 10) + d];
    float ev = g_wsum[b] * bv[d];
#pragma unroll
    for (int kc = 0; kc < 16; kc++) ev += g_eligVp[((kc * BS + b) << 10) + d];
    outK[idx] = A * eK0[idx] + ek;
    outV[idx] = A * eV0[idx] + ev;
}

// ---------------- launch ----------------
extern "C" void kernel_launch(void* const* d_in, const int* in_sizes, int n_in,
                              void* d_out, int out_size) {
    const float* x = (const float*)d_in[0];
    const float* h = (const float*)d_in[1];
    const float* sur = (const float*)d_in[2];
    const unsigned int* mask = (const unsigned int*)d_in[3];
    const float* pmK = (const float*)d_in[4];
    const float* pmV = (const float*)d_in[5];
    const float* pa = (const float*)d_in[6];
    const float* eK0 = (const float*)d_in[7];
    const float* eV0 = (const float*)d_in[8];
    const float* Wk = (const float*)d_in[9];
    const float* bk = (const float*)d_in[10];
    const float* Wv = (const float*)d_in[11];
    const float* bv = (const float*)d_in[12];

    float* out = (float*)d_out;
    float* y = out;
    float* outK = out + (size_t)BS * PP * DD;
    float* outV = outK + (size_t)BS * RR * DD;

    static const int READOUT_SMEM = RR * DD * (int)sizeof(float);  // 64 KB
    cudaFuncSetAttribute(readout_kernel,
                         cudaFuncAttributeMaxDynamicSharedMemorySize, READOUT_SMEM);
    cudaFuncSetAttribute(mma_gemm_kernel,
                         cudaFuncAttributeMaxDynamicSharedMemorySize, GSMEM);

    coeff_kernel<<<BS, PP>>>(sur, mask);
    convA_kernel<<<MM * DD / 8 / 256, 256>>>(x);
    convB_kernel<<<DD * DD / 8 / 256, 256>>>(Wk);
    readout_kernel<<<dim3(BS, PP / 16), 256, READOUT_SMEM>>>(x, pmK, pmV, pa, y);
    mma_gemm_kernel<<<dim3(DD / 128, MM / 128), 256, GSMEM>>>(bk);
    hbar_kernel<<<dim3(BS, 1, 8), 256>>>(h);
    eligk_kernel<<<dim3(BS, 2, 8), 256>>>();
    vgemm_kernel<<<dim3(8, 16), 256>>>(Wv);
    expand_kernel<<<(BS * RR * DD + 255) / 256, 256>>>(eK0, eV0, bv, outK, outV);
}